// round 1
// baseline (speedup 1.0000x reference)
#include <cuda_runtime.h>
#include <math.h>
#include <stdint.h>

// Problem constants
#define DD    400
#define BB    64
#define NC_   10
#define NH_   50
#define NHEAD 20
#define DH    20
#define LL    640      // BB*NC_
#define MM    32000    // BB*NC_*NH_
#define BNH   3200     // BB*NH_

// ---------------- device scratch (module-static, no runtime alloc) ----------------
__device__ float g_Hcat[BNH * 1200];
__device__ float g_Hp1 [BNH * 400];
__device__ float g_Cc  [LL * 400];
__device__ float g_Hs  [BNH * 400];
__device__ float g_Cs  [LL * 400];
__device__ float g_Hq3 [BNH * 1200];
__device__ float g_Cq3 [LL * 1200];
__device__ float g_WoT [400 * 400];
__device__ float g_Wm  [400 * 400];
__device__ float g_T1  [BNH * 400];
__device__ float g_T2  [LL * 400];
__device__ float g_tc  [400];
__device__ float g_CA  [LL * 400];
__device__ float g_Xo  [MM * 400];
__device__ float g_hall[MM * 400];
__device__ float g_a1  [MM * 400];
__device__ float g_a2  [MM * 200];
__device__ float g_s   [MM];

// ---------------- small prep kernels ----------------
__global__ void build_hcat_kernel(const float* __restrict__ h, float* __restrict__ out) {
    int idx = blockIdx.x * blockDim.x + threadIdx.x;
    if (idx >= BNH * 1200) return;
    int row = idx / 1200, col = idx % 1200;
    int b = row / NH_, j = row % NH_;
    int part = col / 400, d = col % 400;
    int jj = (part == 0) ? (j + NH_ - 1) % NH_ : ((part == 1) ? j : (j + 1) % NH_);
    out[idx] = h[(b * NH_ + jj) * 400 + d];
}

__global__ void transpose400_kernel(const float* __restrict__ Wo, float* __restrict__ WoT) {
    int idx = blockIdx.x * blockDim.x + threadIdx.x;
    if (idx >= 400 * 400) return;
    int r = idx / 400, c = idx % 400;
    WoT[idx] = Wo[c * 400 + r];   // WoT[k][t] = Wo[t][k]
}

__global__ void tc_kernel(const float* __restrict__ b1, const float* __restrict__ bo,
                          const float* __restrict__ b3, const float* __restrict__ W3,
                          float* __restrict__ tc) {
    int r = blockIdx.x * blockDim.x + threadIdx.x;
    if (r >= 400) return;
    float acc = b3[r];
    for (int d = 0; d < 400; d++)
        acc += b1[d] * W3[r * 800 + d] + bo[d] * W3[r * 800 + 400 + d];
    tc[r] = acc;
}

// ---------------- generic SGEMM: C(MxN) = A(MxK,lda) @ B(NxK,ldb)^T + epilogue ----------------
// MODE 0: none | 1: +aux0[col] | 2: tanh(x+aux0[col]) | 3: +T1[(b,j)]+T2[(b,i)]+tc[col]
// MODE 4: tanh(x + aux0[(b,i)*N+col])       (modes 3/4 assume M==32000 row layout)
#define GBM 128
#define GBN 128
#define GBK 8
#define GTM 8
#define GTN 8

template <int MODE>
__global__ __launch_bounds__(256) void gemm_abt(
    const float* __restrict__ A, int lda,
    const float* __restrict__ B, int ldb,
    float* __restrict__ C, int ldc,
    int M, int N, int K,
    const float* __restrict__ aux0,
    const float* __restrict__ aux1,
    const float* __restrict__ aux2)
{
    __shared__ float As[GBK][GBM + 4];
    __shared__ float Bs[GBK][GBN + 4];

    int tid = threadIdx.x;
    int tx = tid & 15;          // 0..15 -> 8 cols each
    int ty = tid >> 4;          // 0..15 -> 8 rows each
    int row0 = blockIdx.y * GBM;
    int col0 = blockIdx.x * GBN;

    int lr = tid >> 1;          // 0..127 (row/col within tile for loads)
    int lk = (tid & 1) * 4;     // 0 or 4

    float acc[GTM][GTN];
    #pragma unroll
    for (int i = 0; i < GTM; i++)
        #pragma unroll
        for (int j = 0; j < GTN; j++) acc[i][j] = 0.f;

    for (int k0 = 0; k0 < K; k0 += GBK) {
        float4 va = make_float4(0.f, 0.f, 0.f, 0.f);
        float4 vb = make_float4(0.f, 0.f, 0.f, 0.f);
        int gr = row0 + lr;
        if (gr < M) va = *reinterpret_cast<const float4*>(A + (size_t)gr * lda + k0 + lk);
        int gc = col0 + lr;
        if (gc < N) vb = *reinterpret_cast<const float4*>(B + (size_t)gc * ldb + k0 + lk);
        As[lk + 0][lr] = va.x; As[lk + 1][lr] = va.y; As[lk + 2][lr] = va.z; As[lk + 3][lr] = va.w;
        Bs[lk + 0][lr] = vb.x; Bs[lk + 1][lr] = vb.y; Bs[lk + 2][lr] = vb.z; Bs[lk + 3][lr] = vb.w;
        __syncthreads();

        #pragma unroll
        for (int kk = 0; kk < GBK; kk++) {
            float ar[GTM], br[GTN];
            const float4* ap = reinterpret_cast<const float4*>(&As[kk][ty * GTM]);
            const float4* bp = reinterpret_cast<const float4*>(&Bs[kk][tx * GTN]);
            float4 a0 = ap[0], a1 = ap[1];
            float4 b0 = bp[0], b1 = bp[1];
            ar[0]=a0.x; ar[1]=a0.y; ar[2]=a0.z; ar[3]=a0.w; ar[4]=a1.x; ar[5]=a1.y; ar[6]=a1.z; ar[7]=a1.w;
            br[0]=b0.x; br[1]=b0.y; br[2]=b0.z; br[3]=b0.w; br[4]=b1.x; br[5]=b1.y; br[6]=b1.z; br[7]=b1.w;
            #pragma unroll
            for (int i = 0; i < GTM; i++)
                #pragma unroll
                for (int j = 0; j < GTN; j++)
                    acc[i][j] += ar[i] * br[j];
        }
        __syncthreads();
    }

    #pragma unroll
    for (int i = 0; i < GTM; i++) {
        int r = row0 + ty * GTM + i;
        if (r >= M) continue;
        int bb = r / 500;          // b      (valid for M==32000 modes)
        int ii = (r / 50) % 10;    // i
        int jj = r % 50;           // j
        #pragma unroll
        for (int j = 0; j < GTN; j++) {
            int cidx = col0 + tx * GTN + j;
            if (cidx >= N) continue;
            float v = acc[i][j];
            if (MODE == 1) v += aux0[cidx];
            if (MODE == 2) v = tanhf(v + aux0[cidx]);
            if (MODE == 3) v += aux0[(size_t)(bb * 50 + jj) * N + cidx]
                             + aux1[(size_t)(bb * 10 + ii) * N + cidx]
                             + aux2[cidx];
            if (MODE == 4) v = tanhf(v + aux0[(size_t)(bb * 10 + ii) * N + cidx]);
            C[(size_t)r * ldc + cidx] = v;
        }
    }
}

// ---------------- attention: one block per (n, head) ----------------
// q[l,n] = Cq3[l, h*20+d] + Hq3[(b(l)*50+n), h*20+d]; k/v at +400/+800.
// No max-subtraction: logits ~ N(0, 0.05), exp is safe.
__global__ __launch_bounds__(640) void attn_kernel(
    const float* __restrict__ Cq3, const float* __restrict__ Hq3,
    float* __restrict__ Xo)
{
    __shared__ float Ks[256 * DH];
    __shared__ float Vs[256 * DH];

    int n = blockIdx.x / NHEAD;
    int h = blockIdx.x % NHEAD;
    int l = threadIdx.x;              // 640 threads == 640 rows

    const float scale = 0.22360679774997896f;  // 1/sqrt(20)
    float q[DH], acc[DH];
    float Z = 0.f;
    int qrow = (l / NC_) * NH_ + n;
    #pragma unroll
    for (int d = 0; d < DH; d++) {
        q[d] = (Cq3[l * 1200 + h * DH + d] + Hq3[qrow * 1200 + h * DH + d]) * scale;
        acc[d] = 0.f;
    }

    for (int m0 = 0; m0 < LL; m0 += 256) {
        int cnt = min(256, LL - m0);
        __syncthreads();
        for (int idx = threadIdx.x; idx < cnt * DH; idx += blockDim.x) {
            int mm = idx / DH, d = idx % DH;
            int m = m0 + mm;
            int hr = (m / NC_) * NH_ + n;
            int off = h * DH + d;
            Ks[idx] = Cq3[m * 1200 + 400 + off] + Hq3[hr * 1200 + 400 + off];
            Vs[idx] = Cq3[m * 1200 + 800 + off] + Hq3[hr * 1200 + 800 + off];
        }
        __syncthreads();
        for (int mm = 0; mm < cnt; mm++) {
            const float4* kp = reinterpret_cast<const float4*>(Ks + mm * DH);
            float s0 = 0.f, s1 = 0.f;
            #pragma unroll
            for (int t = 0; t < 5; t++) {
                float4 kv = kp[t];
                if (t & 1) { s1 += q[4*t]*kv.x + q[4*t+1]*kv.y + q[4*t+2]*kv.z + q[4*t+3]*kv.w; }
                else       { s0 += q[4*t]*kv.x + q[4*t+1]*kv.y + q[4*t+2]*kv.z + q[4*t+3]*kv.w; }
            }
            float e = __expf(s0 + s1);
            Z += e;
            const float4* vp = reinterpret_cast<const float4*>(Vs + mm * DH);
            #pragma unroll
            for (int t = 0; t < 5; t++) {
                float4 vv = vp[t];
                acc[4*t]   += e * vv.x;
                acc[4*t+1] += e * vv.y;
                acc[4*t+2] += e * vv.z;
                acc[4*t+3] += e * vv.w;
            }
        }
    }

    float iz = 1.f / Z;
    float* out = Xo + ((size_t)l * NH_ + n) * 400 + h * DH;
    #pragma unroll
    for (int d = 0; d < DH; d++) out[d] = acc[d] * iz;
}

// ---------------- score: s[m] = a2[m,:]·Wa3 + ba3 ----------------
__global__ void score_kernel(const float* __restrict__ a2, const float* __restrict__ Wa3,
                             const float* __restrict__ ba3, float* __restrict__ s)
{
    int row = blockIdx.x * 8 + threadIdx.y;
    if (row >= MM) return;
    int lane = threadIdx.x;
    float acc = 0.f;
    for (int d = lane; d < 200; d += 32) acc += a2[(size_t)row * 200 + d] * Wa3[d];
    #pragma unroll
    for (int o = 16; o > 0; o >>= 1) acc += __shfl_xor_sync(0xffffffffu, acc, o);
    if (lane == 0) s[row] = acc + ba3[0];
}

// ---------------- softmax over j + weighted sum -> u ----------------
__global__ void softmax_u_kernel(const float* __restrict__ s, const float* __restrict__ hall,
                                 float* __restrict__ u)
{
    __shared__ float a[NH_];
    int bi = blockIdx.x;      // 0..639
    if (threadIdx.x == 0) {
        float mx = -1e30f;
        for (int j = 0; j < NH_; j++) mx = fmaxf(mx, s[bi * NH_ + j]);
        float Z = 0.f;
        for (int j = 0; j < NH_; j++) { float e = __expf(s[bi * NH_ + j] - mx); a[j] = e; Z += e; }
        float iz = 1.f / Z;
        for (int j = 0; j < NH_; j++) a[j] *= iz;
    }
    __syncthreads();
    for (int d = threadIdx.x; d < 400; d += blockDim.x) {
        float acc = 0.f;
        for (int j = 0; j < NH_; j++)
            acc += a[j] * hall[((size_t)bi * NH_ + j) * 400 + d];
        u[(size_t)bi * 400 + d] = acc;
    }
}

// ---------------- launch ----------------
static inline dim3 ggrid(int M, int N) { return dim3((N + GBN - 1) / GBN, (M + GBM - 1) / GBM); }

extern "C" void kernel_launch(void* const* d_in, const int* in_sizes, int n_in,
                              void* d_out, int out_size)
{
    const float* h    = (const float*)d_in[0];
    const float* c    = (const float*)d_in[2];
    const float* W1   = (const float*)d_in[4];
    const float* b1   = (const float*)d_in[5];
    const float* W2   = (const float*)d_in[6];
    const float* b2   = (const float*)d_in[7];
    const float* W3   = (const float*)d_in[8];
    const float* b3   = (const float*)d_in[9];
    const float* Wa1  = (const float*)d_in[10];
    const float* ba1  = (const float*)d_in[11];
    const float* Wa2  = (const float*)d_in[12];
    const float* ba2  = (const float*)d_in[13];
    const float* Wa3  = (const float*)d_in[14];
    const float* ba3  = (const float*)d_in[15];
    const float* Wqkv = (const float*)d_in[16];
    const float* bqkv = (const float*)d_in[17];
    const float* Wo   = (const float*)d_in[18];
    const float* bo   = (const float*)d_in[19];
    float* u = (float*)d_out;

    float *Hcat, *Hp1, *Cc, *Hs, *Cs, *Hq3, *Cq3, *WoT, *Wm, *T1, *T2, *tc, *CA, *Xo, *hall, *a1, *a2, *sc;
    cudaGetSymbolAddress((void**)&Hcat, g_Hcat);
    cudaGetSymbolAddress((void**)&Hp1,  g_Hp1);
    cudaGetSymbolAddress((void**)&Cc,   g_Cc);
    cudaGetSymbolAddress((void**)&Hs,   g_Hs);
    cudaGetSymbolAddress((void**)&Cs,   g_Cs);
    cudaGetSymbolAddress((void**)&Hq3,  g_Hq3);
    cudaGetSymbolAddress((void**)&Cq3,  g_Cq3);
    cudaGetSymbolAddress((void**)&WoT,  g_WoT);
    cudaGetSymbolAddress((void**)&Wm,   g_Wm);
    cudaGetSymbolAddress((void**)&T1,   g_T1);
    cudaGetSymbolAddress((void**)&T2,   g_T2);
    cudaGetSymbolAddress((void**)&tc,   g_tc);
    cudaGetSymbolAddress((void**)&CA,   g_CA);
    cudaGetSymbolAddress((void**)&Xo,   g_Xo);
    cudaGetSymbolAddress((void**)&hall, g_hall);
    cudaGetSymbolAddress((void**)&a1,   g_a1);
    cudaGetSymbolAddress((void**)&a2,   g_a2);
    cudaGetSymbolAddress((void**)&sc,   g_s);

    // prep
    build_hcat_kernel<<<(BNH * 1200 + 255) / 256, 256>>>(h, Hcat);
    transpose400_kernel<<<(400 * 400 + 255) / 256, 256>>>(Wo, WoT);
    tc_kernel<<<2, 256>>>(b1, bo, b3, W3, tc);

    // decomposed small GEMMs
    gemm_abt<0><<<ggrid(BNH, 400), 256>>>(Hcat, 1200, W1, 1600, Hp1, 400, BNH, 400, 1200, nullptr, nullptr, nullptr);
    gemm_abt<0><<<ggrid(LL, 400),  256>>>(c, 400, W1 + 1200, 1600, Cc, 400, LL, 400, 400, nullptr, nullptr, nullptr);
    gemm_abt<0><<<ggrid(BNH, 400), 256>>>(h, 400, W2 + 400, 800, Hs, 400, BNH, 400, 400, nullptr, nullptr, nullptr);
    gemm_abt<1><<<ggrid(LL, 400),  256>>>(c, 400, W2, 800, Cs, 400, LL, 400, 400, b2, nullptr, nullptr);
    gemm_abt<0><<<ggrid(BNH, 1200), 256>>>(Hs, 400, Wqkv, 400, Hq3, 1200, BNH, 1200, 400, nullptr, nullptr, nullptr);
    gemm_abt<1><<<ggrid(LL, 1200),  256>>>(Cs, 400, Wqkv, 400, Cq3, 1200, LL, 1200, 400, bqkv, nullptr, nullptr);
    gemm_abt<0><<<ggrid(400, 400), 256>>>(W3 + 400, 800, WoT, 400, Wm, 400, 400, 400, 400, nullptr, nullptr, nullptr);
    gemm_abt<0><<<ggrid(BNH, 400), 256>>>(Hp1, 400, W3, 800, T1, 400, BNH, 400, 400, nullptr, nullptr, nullptr);
    gemm_abt<0><<<ggrid(LL, 400),  256>>>(Cc, 400, W3, 800, T2, 400, LL, 400, 400, nullptr, nullptr, nullptr);
    gemm_abt<1><<<ggrid(LL, 400),  256>>>(c, 400, Wa1 + 400, 800, CA, 400, LL, 400, 400, ba1, nullptr, nullptr);

    // attention (1000 blocks = 50 n x 20 heads)
    attn_kernel<<<NH_ * NHEAD, 640>>>(Cq3, Hq3, Xo);

    // big fused GEMMs
    gemm_abt<3><<<ggrid(MM, 400), 256>>>(Xo, 400, Wm, 400, hall, 400, MM, 400, 400, T1, T2, tc);
    gemm_abt<4><<<ggrid(MM, 400), 256>>>(hall, 400, Wa1, 800, a1, 400, MM, 400, 400, CA, nullptr, nullptr);
    gemm_abt<2><<<ggrid(MM, 200), 256>>>(a1, 400, Wa2, 400, a2, 200, MM, 200, 400, ba2, nullptr, nullptr);

    // scoring + softmax + weighted sum
    score_kernel<<<MM / 8, dim3(32, 8)>>>(a2, Wa3, ba3, sc);
    softmax_u_kernel<<<LL, 128>>>(sc, hall, u);
}